// round 14
// baseline (speedup 1.0000x reference)
#include <cuda_runtime.h>
#include <cuda_fp16.h>

// LocalAttn, 2-kernel pipeline for GB300 (sm_103a), round 13.
// Kernel A (stage1): 512 threads, 2 threads per pixel.
//   t<256: conv1 -> ftanh -> conv2 -> g_mn (fp16) + v co 0..15 of pixel t
//   t>=256: v co 16..31 of pixel t-256 (q-outer, x re-read per q slice)
//   -> (512,2): <=64 regs, 32 warps/SM (was 24).
// Kernel M (combine): identical to round 12 (19.3us).

typedef unsigned long long ull;

__device__ __half g_v [2u * 8u * 16384u * 32u]; // [img][g][px][32]  16.8 MB
__device__ __half g_mn[2u * 80u * 16384u];      // [img][ch][px]      5.2 MB

__device__ __forceinline__ ull fma2(ull a, ull b, ull c) {
    ull d;
    asm("fma.rn.f32x2 %0, %1, %2, %3;" : "=l"(d) : "l"(a), "l"(b), "l"(c));
    return d;
}
__device__ __forceinline__ float hadd2(ull a) {
    float x, y;
    asm("mov.b64 {%0,%1}, %2;" : "=f"(x), "=f"(y) : "l"(a));
    return x + y;
}
__device__ __forceinline__ float ftanh(float x) {
    float e = __expf(-2.f * fabsf(x));
    float r = __fdividef(1.f - e, 1.f + e);
    return copysignf(r, x);
}

// ============================ Kernel A ============================
// grid (64, 8, 2) = (256-px chunk, group, img), block 512, 2 threads/pixel.
// smem x layout: word = px*36 + ((q ^ ((px>>3)&7))<<2) + w   (c = 4q + w)
__global__ __launch_bounds__(512, 2)
void stage1_kernel(
    const float* __restrict__ x,
    const float* __restrict__ w1, const float* __restrict__ b1,
    const float* __restrict__ g1, const float* __restrict__ be1,
    const float* __restrict__ m1, const float* __restrict__ v1,
    const float* __restrict__ w2, const float* __restrict__ b2,
    const float* __restrict__ g2, const float* __restrict__ be2,
    const float* __restrict__ m2, const float* __restrict__ v2,
    const float* __restrict__ wv)
{
    __shared__ __align__(16) float s_px[256 * 36];   // swizzled [px][ci]; later v
    __shared__ __align__(16) float s_w1g[256];       // w1[g]  (8,32)
    __shared__ __align__(16) float s_wvg[1024];      // wv[g]  (32,32)
    __shared__ __align__(16) float s_w2g[80];        // w2[g]  (10,8)
    __shared__ float s_a1[8], s_c1[8], s_a2[10], s_c2[10];

    const int t    = threadIdx.x;
    const int lane = t & 31;
    const int wq   = t >> 5;          // 0..15
    const int px0  = blockIdx.x * 256;
    const int g    = blockIdx.y;
    const int img  = blockIdx.z;

    // weights + folded BN params
    if (t < 256) s_w1g[t] = w1[g * 256 + t];
    for (int i = t; i < 1024; i += 512) s_wvg[i] = wv[g * 1024 + i];
    if (t < 80) s_w2g[t] = w2[g * 80 + t];
    if (t < 8) {
        int ch = g * 8 + t;
        float inv = g1[ch] * rsqrtf(v1[ch] + 1e-5f);
        s_a1[t] = inv;
        s_c1[t] = b1[ch] * inv + be1[ch] - m1[ch] * inv;
    } else if (t >= 32 && t < 42) {
        int o = t - 32, ch = g * 10 + o;
        float inv = g2[ch] * rsqrtf(v2[ch] + 1e-5f);
        s_a2[o] = inv;
        s_c2[o] = b2[ch] * inv + be2[ch] - m2[ch] * inv;
    }

    // ---- coalesced x staging: warp wq handles channels [wq*2, wq*2+2) ----
    {
        const float* xg = x + ((size_t)img * 256 + g * 32) * 16384 + px0;
        #pragma unroll
        for (int it = 0; it < 2; ++it) {
            int c = wq * 2 + it;
            int q = c >> 2, wrd = c & 3;
            const float* src = xg + (size_t)c * 16384;
            #pragma unroll
            for (int seg = 0; seg < 4; ++seg) {
                int p = (lane + seg * 32) * 2;           // even pixel
                float2 v2 = *(const float2*)(src + p);
                int qs = ((q ^ ((p >> 3) & 7)) << 2) + wrd;
                s_px[p * 36 + qs]       = v2.x;
                s_px[(p + 1) * 36 + qs] = v2.y;
            }
        }
    }
    __syncthreads();

    const int p      = t & 255;
    const int sw     = (p >> 3) & 7;
    const int cohalf = t >> 8;        // 0 or 1
    float* xrow = s_px + p * 36;

    // ---- conv1 -> bn -> tanh -> conv2 -> bn -> g_mn (t<256 only) ----
    if (t < 256) {
        ulonglong2 xr[8];
        #pragma unroll
        for (int q = 0; q < 8; q++)
            xr[q] = *(const ulonglong2*)(xrow + ((q ^ sw) << 2));

        ull acc[8];
        #pragma unroll
        for (int o = 0; o < 8; o++) acc[o] = 0ULL;
        #pragma unroll
        for (int q = 0; q < 8; q++) {
            #pragma unroll
            for (int o = 0; o < 8; o++) {
                ulonglong2 wp = *(const ulonglong2*)(s_w1g + o * 32 + q * 4);
                acc[o] = fma2(xr[q].x, wp.x, acc[o]);
                acc[o] = fma2(xr[q].y, wp.y, acc[o]);
            }
        }
        float tv[8];
        #pragma unroll
        for (int o = 0; o < 8; o++)
            tv[o] = ftanh(hadd2(acc[o]) * s_a1[o] + s_c1[o]);

        __half* mb = g_mn + ((size_t)img * 80 + g * 10) * 16384 + px0 + t;
        #pragma unroll
        for (int o2 = 0; o2 < 10; o2++) {
            float a = 0.f;
            #pragma unroll
            for (int o = 0; o < 8; o++) a += tv[o] * s_w2g[o2 * 8 + o];
            mb[(size_t)o2 * 16384] = __float2half_rn(a * s_a2[o2] + s_c2[o2]);
        }
    }

    // ---- v = wv @ x: this thread's 16 output channels, q-outer ----
    float vres[16];
    {
        const int ob = cohalf * 16;
        ull acc[16];
        #pragma unroll
        for (int o = 0; o < 16; o++) acc[o] = 0ULL;
        #pragma unroll
        for (int q = 0; q < 8; q++) {
            ulonglong2 xq = *(const ulonglong2*)(xrow + ((q ^ sw) << 2));
            #pragma unroll
            for (int o = 0; o < 16; o++) {
                ulonglong2 wp = *(const ulonglong2*)(s_wvg + (ob + o) * 32 + q * 4);
                acc[o] = fma2(xq.x, wp.x, acc[o]);
                acc[o] = fma2(xq.y, wp.y, acc[o]);
            }
        }
        #pragma unroll
        for (int o = 0; o < 16; o++) vres[o] = hadd2(acc[o]);
    }
    __syncthreads();   // all x reads (conv1 + both v halves) complete

    // write v into own row quads: cohalf 0 -> quads 0..3, cohalf 1 -> 4..7
    #pragma unroll
    for (int j = 0; j < 4; j++) {
        int qd = cohalf * 4 + j;
        *(float4*)(xrow + ((qd ^ sw) << 2)) =
            make_float4(vres[j * 4 + 0], vres[j * 4 + 1],
                        vres[j * 4 + 2], vres[j * 4 + 3]);
    }
    __syncthreads();

    // ---- coalesced fp16 store of v ----
    __half* vplane = g_v + ((size_t)(img * 8 + g) * 16384 + px0) * 32;
    #pragma unroll
    for (int i = 0; i < 4; i++) {
        int idx = t + i * 512;          // 2048 4-channel items
        int p2 = idx >> 3, q2 = idx & 7;
        int sp = (p2 >> 3) & 7;
        float4 v4 = *(const float4*)(s_px + p2 * 36 + ((q2 ^ sp) << 2));
        __half2 h0 = __floats2half2_rn(v4.x, v4.y);
        __half2 h1 = __floats2half2_rn(v4.z, v4.w);
        uint2 st;
        st.x = *(unsigned int*)&h0;
        st.y = *(unsigned int*)&h1;
        *(uint2*)(vplane + p2 * 32 + q2 * 4) = st;
    }
}

// ============================ Kernel M ============================
// grid (8, 8, 16): z = img*8 + g. block 256 (one thread per center pixel).
__global__ __launch_bounds__(256, 4)
void combine_kernel(float* __restrict__ out)
{
    __shared__ __align__(16) float s_v[324 * 36];   // [hp][co] pitch 36 (fp32)

    const int t   = threadIdx.x;
    const int ty  = t >> 4, tx = t & 15;
    const int w0  = blockIdx.x * 16;
    const int h0  = blockIdx.y * 16;
    const int img = blockIdx.z >> 3;
    const int g   = blockIdx.z & 7;
    const int h   = h0 + ty, w = w0 + tx;
    const int px  = h * 128 + w;

    // ---- v halo gather: 16B loads (8 fp16 channels per item) ----
    const __half* vt = g_v + (size_t)(img * 8 + g) * (16384u * 32u);
    #pragma unroll
    for (int i = 0; i < 6; i++) {
        int idx = t + i * 256;          // 1296 items = 324 px * 4 chunks of 8ch
        if (idx < 1296) {
            int hp = idx >> 2, q = idx & 3;
            int hy = hp / 18, hx = hp - hy * 18;
            int hh = h0 + hy - 1, ww = w0 + hx - 1;
            uint4 raw = make_uint4(0u, 0u, 0u, 0u);
            if (((unsigned)hh < 128u) & ((unsigned)ww < 128u))
                raw = *(const uint4*)(vt + (size_t)(hh * 128 + ww) * 32 + q * 8);
            float2 f0 = __half22float2(*(__half2*)&raw.x);
            float2 f1 = __half22float2(*(__half2*)&raw.y);
            float2 f2 = __half22float2(*(__half2*)&raw.z);
            float2 f3 = __half22float2(*(__half2*)&raw.w);
            float* dst = s_v + hp * 36 + q * 8;
            *(float4*)(dst)     = make_float4(f0.x, f0.y, f1.x, f1.y);
            *(float4*)(dst + 4) = make_float4(f2.x, f2.y, f3.x, f3.y);
        }
    }

    // ---- logits: mask (9 strided coalesced) + neighbor (9 predicated), fp16 ----
    float a[9];
    {
        const __half* nbg   = g_mn + ((size_t)img * 80 + g) * 16384;
        const __half* mbase = g_mn + ((size_t)img * 80 + 8 + g * 9) * 16384 + px;
        #pragma unroll
        for (int k = 0; k < 9; k++) {
            int i = k / 3, j = k - i * 3;
            int hh = h + i - 1, ww = w + j - 1;
            float nb = 0.f;
            if (((unsigned)hh < 128u) & ((unsigned)ww < 128u))
                nb = __half2float(nbg[hh * 128 + ww]);
            a[k] = __half2float(mbase[(size_t)k * 16384]) + nb;
        }
        float mx = a[0];
        #pragma unroll
        for (int k = 1; k < 9; k++) mx = fmaxf(mx, a[k]);
        float s = 0.f;
        #pragma unroll
        for (int k = 0; k < 9; k++) { a[k] = __expf(a[k] - mx); s += a[k]; }
        float inv = 1.f / s;
        #pragma unroll
        for (int k = 0; k < 9; k++) a[k] *= inv;
    }
    __syncthreads();

    // ---- combine: out[c] = sum_k a[k] * v[c] at neighbor k ----
    {
        int hpk[9];
        #pragma unroll
        for (int k = 0; k < 9; k++) {
            int i = k / 3, j = k - i * 3;
            hpk[k] = ((ty + i) * 18 + (tx + j)) * 36;
        }
        float* ob = out + ((size_t)img * 256 + g * 32) * 16384 + px;
        #pragma unroll
        for (int c4 = 0; c4 < 8; c4++) {
            float ax = 0.f, ay = 0.f, az = 0.f, aw = 0.f;
            #pragma unroll
            for (int k = 0; k < 9; k++) {
                float4 vv = *(const float4*)(s_v + hpk[k] + c4 * 4);
                ax += a[k] * vv.x; ay += a[k] * vv.y;
                az += a[k] * vv.z; aw += a[k] * vv.w;
            }
            ob[(size_t)(c4 * 4 + 0) * 16384] = ax;
            ob[(size_t)(c4 * 4 + 1) * 16384] = ay;
            ob[(size_t)(c4 * 4 + 2) * 16384] = az;
            ob[(size_t)(c4 * 4 + 3) * 16384] = aw;
        }
    }
}

extern "C" void kernel_launch(void* const* d_in, const int* in_sizes, int n_in,
                              void* d_out, int out_size) {
    const float* x   = (const float*)d_in[0];
    const float* w1  = (const float*)d_in[1];
    const float* b1  = (const float*)d_in[2];
    const float* g1  = (const float*)d_in[3];
    const float* be1 = (const float*)d_in[4];
    const float* m1  = (const float*)d_in[5];
    const float* v1  = (const float*)d_in[6];
    const float* w2  = (const float*)d_in[7];
    const float* b2  = (const float*)d_in[8];
    const float* g2  = (const float*)d_in[9];
    const float* be2 = (const float*)d_in[10];
    const float* m2  = (const float*)d_in[11];
    const float* v2  = (const float*)d_in[12];
    const float* wv  = (const float*)d_in[13];
    float* out = (float*)d_out;

    stage1_kernel<<<dim3(64, 8, 2), 512>>>(x, w1, b1, g1, be1, m1, v1,
                                           w2, b2, g2, be2, m2, v2, wv);
    combine_kernel<<<dim3(8, 8, 16), 256>>>(out);
}

// round 15
// speedup vs baseline: 1.0345x; 1.0345x over previous
#include <cuda_runtime.h>
#include <cuda_fp16.h>

// LocalAttn, 2-kernel pipeline for GB300 (sm_103a), round 15.
// = round-12 (best, 51.7us) with ONE change: stage1 __launch_bounds__(256,2)
//   (128-reg cap instead of 84) to eliminate suspected spills in the v-conv
//   loop. Round 13 showed stage1 is insensitive to occupancy (24 vs 32 warps),
//   so trading 24->16 warps for a spill-free hot loop is the right direction.
// Kernel M (combine): byte-identical to round 12.

typedef unsigned long long ull;

__device__ __half g_v [2u * 8u * 16384u * 32u]; // [img][g][px][32]  16.8 MB
__device__ __half g_mn[2u * 80u * 16384u];      // [img][ch][px]      5.2 MB

__device__ __forceinline__ ull fma2(ull a, ull b, ull c) {
    ull d;
    asm("fma.rn.f32x2 %0, %1, %2, %3;" : "=l"(d) : "l"(a), "l"(b), "l"(c));
    return d;
}
__device__ __forceinline__ float hadd2(ull a) {
    float x, y;
    asm("mov.b64 {%0,%1}, %2;" : "=f"(x), "=f"(y) : "l"(a));
    return x + y;
}
__device__ __forceinline__ float ftanh(float x) {
    float e = __expf(-2.f * fabsf(x));
    float r = __fdividef(1.f - e, 1.f + e);
    return copysignf(r, x);
}

// ============================ Kernel A ============================
// grid (64, 8, 2) = (px chunk, group, img), block 256, one thread per pixel.
// smem x layout: word = px*36 + ((q ^ ((px>>3)&7))<<2) + w   (c = 4q + w)
__global__ __launch_bounds__(256, 2)
void stage1_kernel(
    const float* __restrict__ x,
    const float* __restrict__ w1, const float* __restrict__ b1,
    const float* __restrict__ g1, const float* __restrict__ be1,
    const float* __restrict__ m1, const float* __restrict__ v1,
    const float* __restrict__ w2, const float* __restrict__ b2,
    const float* __restrict__ g2, const float* __restrict__ be2,
    const float* __restrict__ m2, const float* __restrict__ v2,
    const float* __restrict__ wv)
{
    __shared__ __align__(16) float s_px[256 * 36];   // swizzled [px][ci]; later v
    __shared__ __align__(16) float s_w1g[256];       // w1[g]  (8,32)
    __shared__ __align__(16) float s_wvg[1024];      // wv[g]  (32,32)
    __shared__ __align__(16) float s_w2g[80];        // w2[g]  (10,8)
    __shared__ float s_a1[8], s_c1[8], s_a2[10], s_c2[10];

    const int t    = threadIdx.x;
    const int lane = t & 31;
    const int wq   = t >> 5;
    const int px0  = blockIdx.x * 256;
    const int g    = blockIdx.y;
    const int img  = blockIdx.z;

    // weights + folded BN params
    s_w1g[t] = w1[g * 256 + t];
    for (int i = t; i < 1024; i += 256) s_wvg[i] = wv[g * 1024 + i];
    if (t < 80) s_w2g[t] = w2[g * 80 + t];
    if (t < 8) {
        int ch = g * 8 + t;
        float inv = g1[ch] * rsqrtf(v1[ch] + 1e-5f);
        s_a1[t] = inv;
        s_c1[t] = b1[ch] * inv + be1[ch] - m1[ch] * inv;
    } else if (t >= 32 && t < 42) {
        int o = t - 32, ch = g * 10 + o;
        float inv = g2[ch] * rsqrtf(v2[ch] + 1e-5f);
        s_a2[o] = inv;
        s_c2[o] = b2[ch] * inv + be2[ch] - m2[ch] * inv;
    }

    // ---- coalesced x staging: warp wq handles channels [wq*4, wq*4+4) ----
    {
        const float* xg = x + ((size_t)img * 256 + g * 32) * 16384 + px0;
        #pragma unroll
        for (int it = 0; it < 4; ++it) {
            int c = wq * 4 + it;
            int q = c >> 2, wrd = c & 3;
            const float* src = xg + (size_t)c * 16384;
            #pragma unroll
            for (int seg = 0; seg < 4; ++seg) {
                int p = (lane + seg * 32) * 2;           // even pixel
                float2 v2 = *(const float2*)(src + p);
                int qs = ((q ^ ((p >> 3) & 7)) << 2) + wrd;
                s_px[p * 36 + qs]       = v2.x;
                s_px[(p + 1) * 36 + qs] = v2.y;
            }
        }
    }
    __syncthreads();

    // pull own x row into registers (logical quad order, physical swizzled)
    const int sw = (t >> 3) & 7;
    float* xrow = s_px + t * 36;
    ulonglong2 xr[8];
    #pragma unroll
    for (int q = 0; q < 8; q++)
        xr[q] = *(const ulonglong2*)(xrow + ((q ^ sw) << 2));

    // ---- conv1 -> bn -> tanh -> conv2 -> bn -> g_mn (fp16) ----
    {
        ull acc[8];
        #pragma unroll
        for (int o = 0; o < 8; o++) acc[o] = 0ULL;
        #pragma unroll
        for (int q = 0; q < 8; q++) {
            #pragma unroll
            for (int o = 0; o < 8; o++) {
                ulonglong2 wp = *(const ulonglong2*)(s_w1g + o * 32 + q * 4);
                acc[o] = fma2(xr[q].x, wp.x, acc[o]);
                acc[o] = fma2(xr[q].y, wp.y, acc[o]);
            }
        }
        float tv[8];
        #pragma unroll
        for (int o = 0; o < 8; o++)
            tv[o] = ftanh(hadd2(acc[o]) * s_a1[o] + s_c1[o]);

        __half* mb = g_mn + ((size_t)img * 80 + g * 10) * 16384 + px0 + t;
        #pragma unroll
        for (int o2 = 0; o2 < 10; o2++) {
            float a = 0.f;
            #pragma unroll
            for (int o = 0; o < 8; o++) a += tv[o] * s_w2g[o2 * 8 + o];
            mb[(size_t)o2 * 16384] = __float2half_rn(a * s_a2[o2] + s_c2[o2]);
        }
    }

    // ---- v = wv @ x in 4 chunks of 8 outputs; write into own swizzled row ----
    #pragma unroll
    for (int ch = 0; ch < 4; ch++) {
        ull acc[8];
        #pragma unroll
        for (int o = 0; o < 8; o++) acc[o] = 0ULL;
        #pragma unroll
        for (int q = 0; q < 8; q++) {
            #pragma unroll
            for (int o = 0; o < 8; o++) {
                ulonglong2 wp = *(const ulonglong2*)(s_wvg + (ch * 8 + o) * 32 + q * 4);
                acc[o] = fma2(xr[q].x, wp.x, acc[o]);
                acc[o] = fma2(xr[q].y, wp.y, acc[o]);
            }
        }
        float4 r;
        r.x = hadd2(acc[0]); r.y = hadd2(acc[1]);
        r.z = hadd2(acc[2]); r.w = hadd2(acc[3]);
        *(float4*)(xrow + (((2 * ch)     ^ sw) << 2)) = r;
        r.x = hadd2(acc[4]); r.y = hadd2(acc[5]);
        r.z = hadd2(acc[6]); r.w = hadd2(acc[7]);
        *(float4*)(xrow + (((2 * ch + 1) ^ sw) << 2)) = r;
    }
    __syncthreads();

    // ---- coalesced fp16 store of v: warp writes 256B contiguous ----
    __half* vplane = g_v + ((size_t)(img * 8 + g) * 16384 + px0) * 32;
    #pragma unroll
    for (int i = 0; i < 8; i++) {
        int idx = t + i * 256;          // 2048 4-channel items
        int p = idx >> 3, q = idx & 7;
        int sp = (p >> 3) & 7;
        float4 v4 = *(const float4*)(s_px + p * 36 + ((q ^ sp) << 2));
        __half2 h0 = __floats2half2_rn(v4.x, v4.y);
        __half2 h1 = __floats2half2_rn(v4.z, v4.w);
        uint2 st;
        st.x = *(unsigned int*)&h0;
        st.y = *(unsigned int*)&h1;
        *(uint2*)(vplane + p * 32 + q * 4) = st;
    }
}

// ============================ Kernel M ============================
// grid (8, 8, 16): z = img*8 + g. block 256 (one thread per center pixel).
__global__ __launch_bounds__(256, 4)
void combine_kernel(float* __restrict__ out)
{
    __shared__ __align__(16) float s_v[324 * 36];   // [hp][co] pitch 36 (fp32)

    const int t   = threadIdx.x;
    const int ty  = t >> 4, tx = t & 15;
    const int w0  = blockIdx.x * 16;
    const int h0  = blockIdx.y * 16;
    const int img = blockIdx.z >> 3;
    const int g   = blockIdx.z & 7;
    const int h   = h0 + ty, w = w0 + tx;
    const int px  = h * 128 + w;

    // ---- v halo gather: 16B loads (8 fp16 channels per item) ----
    const __half* vt = g_v + (size_t)(img * 8 + g) * (16384u * 32u);
    #pragma unroll
    for (int i = 0; i < 6; i++) {
        int idx = t + i * 256;          // 1296 items = 324 px * 4 chunks of 8ch
        if (idx < 1296) {
            int hp = idx >> 2, q = idx & 3;
            int hy = hp / 18, hx = hp - hy * 18;
            int hh = h0 + hy - 1, ww = w0 + hx - 1;
            uint4 raw = make_uint4(0u, 0u, 0u, 0u);
            if (((unsigned)hh < 128u) & ((unsigned)ww < 128u))
                raw = *(const uint4*)(vt + (size_t)(hh * 128 + ww) * 32 + q * 8);
            float2 f0 = __half22float2(*(__half2*)&raw.x);
            float2 f1 = __half22float2(*(__half2*)&raw.y);
            float2 f2 = __half22float2(*(__half2*)&raw.z);
            float2 f3 = __half22float2(*(__half2*)&raw.w);
            float* dst = s_v + hp * 36 + q * 8;
            *(float4*)(dst)     = make_float4(f0.x, f0.y, f1.x, f1.y);
            *(float4*)(dst + 4) = make_float4(f2.x, f2.y, f3.x, f3.y);
        }
    }

    // ---- logits: mask (9 strided coalesced) + neighbor (9 predicated), fp16 ----
    float a[9];
    {
        const __half* nbg   = g_mn + ((size_t)img * 80 + g) * 16384;
        const __half* mbase = g_mn + ((size_t)img * 80 + 8 + g * 9) * 16384 + px;
        #pragma unroll
        for (int k = 0; k < 9; k++) {
            int i = k / 3, j = k - i * 3;
            int hh = h + i - 1, ww = w + j - 1;
            float nb = 0.f;
            if (((unsigned)hh < 128u) & ((unsigned)ww < 128u))
                nb = __half2float(nbg[hh * 128 + ww]);
            a[k] = __half2float(mbase[(size_t)k * 16384]) + nb;
        }
        float mx = a[0];
        #pragma unroll
        for (int k = 1; k < 9; k++) mx = fmaxf(mx, a[k]);
        float s = 0.f;
        #pragma unroll
        for (int k = 0; k < 9; k++) { a[k] = __expf(a[k] - mx); s += a[k]; }
        float inv = 1.f / s;
        #pragma unroll
        for (int k = 0; k < 9; k++) a[k] *= inv;
    }
    __syncthreads();

    // ---- combine: out[c] = sum_k a[k] * v[c] at neighbor k ----
    {
        int hpk[9];
        #pragma unroll
        for (int k = 0; k < 9; k++) {
            int i = k / 3, j = k - i * 3;
            hpk[k] = ((ty + i) * 18 + (tx + j)) * 36;
        }
        float* ob = out + ((size_t)img * 256 + g * 32) * 16384 + px;
        #pragma unroll
        for (int c4 = 0; c4 < 8; c4++) {
            float ax = 0.f, ay = 0.f, az = 0.f, aw = 0.f;
            #pragma unroll
            for (int k = 0; k < 9; k++) {
                float4 vv = *(const float4*)(s_v + hpk[k] + c4 * 4);
                ax += a[k] * vv.x; ay += a[k] * vv.y;
                az += a[k] * vv.z; aw += a[k] * vv.w;
            }
            ob[(size_t)(c4 * 4 + 0) * 16384] = ax;
            ob[(size_t)(c4 * 4 + 1) * 16384] = ay;
            ob[(size_t)(c4 * 4 + 2) * 16384] = az;
            ob[(size_t)(c4 * 4 + 3) * 16384] = aw;
        }
    }
}

extern "C" void kernel_launch(void* const* d_in, const int* in_sizes, int n_in,
                              void* d_out, int out_size) {
    const float* x   = (const float*)d_in[0];
    const float* w1  = (const float*)d_in[1];
    const float* b1  = (const float*)d_in[2];
    const float* g1  = (const float*)d_in[3];
    const float* be1 = (const float*)d_in[4];
    const float* m1  = (const float*)d_in[5];
    const float* v1  = (const float*)d_in[6];
    const float* w2  = (const float*)d_in[7];
    const float* b2  = (const float*)d_in[8];
    const float* g2  = (const float*)d_in[9];
    const float* be2 = (const float*)d_in[10];
    const float* m2  = (const float*)d_in[11];
    const float* v2  = (const float*)d_in[12];
    const float* wv  = (const float*)d_in[13];
    float* out = (float*)d_out;

    stage1_kernel<<<dim3(64, 8, 2), 256>>>(x, w1, b1, g1, be1, m1, v1,
                                           w2, b2, g2, be2, m2, v2, wv);
    combine_kernel<<<dim3(8, 8, 16), 256>>>(out);
}

// round 16
// speedup vs baseline: 1.2500x; 1.2083x over previous
#include <cuda_runtime.h>
#include <cuda_fp16.h>

// LocalAttn, 2-kernel pipeline for GB300 (sm_103a), round 16.
// stage1's v-conv moved to the TENSOR pipe (HMMA m16n8k16, fp16 in / fp32 acc):
//   it was 80% of the FMA-pipe work that bounds stage1 (f32x2 is NOT double-rate).
//   conv1 -> mn stays scalar fp32 (protects logits). g_v layout unchanged.
// Kernel M (combine): byte-identical to round 12/15.

typedef unsigned long long ull;
typedef unsigned int uint;

__device__ __half g_v [2u * 8u * 16384u * 32u]; // [img][g][px][32]  16.8 MB
__device__ __half g_mn[2u * 80u * 16384u];      // [img][ch][px]      5.2 MB

__device__ __forceinline__ ull fma2(ull a, ull b, ull c) {
    ull d;
    asm("fma.rn.f32x2 %0, %1, %2, %3;" : "=l"(d) : "l"(a), "l"(b), "l"(c));
    return d;
}
__device__ __forceinline__ float hadd2(ull a) {
    float x, y;
    asm("mov.b64 {%0,%1}, %2;" : "=f"(x), "=f"(y) : "l"(a));
    return x + y;
}
__device__ __forceinline__ float ftanh(float x) {
    float e = __expf(-2.f * fabsf(x));
    float r = __fdividef(1.f - e, 1.f + e);
    return copysignf(r, x);
}

// ---- dynamic smem layout (bytes) ----
// s_px  fp32 [256*36]  @0      (36864)  swizzled x rows, conv1 input
// s_w1g fp32 [256]     @36864  (1024)
// s_w2g fp32 [80]      @37888  (320)
// s_a1/c1/a2/c2        @38208  (144) -> pad 38400
// x_h  half [32][264]  @38400  (16896)  channel-major fp16 x for HMMA B
// w_h  half [32][40]   @55296  (2560)   wv fp16 for HMMA A (pitch 40: LDSM conflict-free)
// s_vh half [256][40]  @57856  (20480)  v writeout tile [px][co], pitch 40
static const int S_SMEM = 78336;

// ============================ Kernel A ============================
// grid (64, 8, 2) = (px chunk, group, img), block 256, one thread per pixel.
__global__ __launch_bounds__(256, 2)
void stage1_kernel(
    const float* __restrict__ x,
    const float* __restrict__ w1, const float* __restrict__ b1,
    const float* __restrict__ g1, const float* __restrict__ be1,
    const float* __restrict__ m1, const float* __restrict__ v1,
    const float* __restrict__ w2, const float* __restrict__ b2,
    const float* __restrict__ g2, const float* __restrict__ be2,
    const float* __restrict__ m2, const float* __restrict__ v2,
    const float* __restrict__ wv)
{
    extern __shared__ __align__(16) char smraw[];
    float*  s_px  = (float*)(smraw);
    float*  s_w1g = (float*)(smraw + 36864);
    float*  s_w2g = (float*)(smraw + 37888);
    float*  s_a1  = (float*)(smraw + 38208);
    float*  s_c1  = (float*)(smraw + 38240);
    float*  s_a2  = (float*)(smraw + 38272);
    float*  s_c2  = (float*)(smraw + 38312);
    __half* x_h   = (__half*)(smraw + 38400);
    __half* w_h   = (__half*)(smraw + 55296);
    __half* s_vh  = (__half*)(smraw + 57856);

    const int t    = threadIdx.x;
    const int lane = t & 31;
    const int wq   = t >> 5;
    const int px0  = blockIdx.x * 256;
    const int g    = blockIdx.y;
    const int img  = blockIdx.z;

    // weights + folded BN params
    s_w1g[t] = w1[g * 256 + t];
    for (int i = t; i < 1024; i += 256) {
        int co = i >> 5, ci = i & 31;
        w_h[co * 40 + ci] = __float2half_rn(wv[g * 1024 + i]);
    }
    if (t < 80) s_w2g[t] = w2[g * 80 + t];
    if (t < 8) {
        int ch = g * 8 + t;
        float inv = g1[ch] * rsqrtf(v1[ch] + 1e-5f);
        s_a1[t] = inv;
        s_c1[t] = b1[ch] * inv + be1[ch] - m1[ch] * inv;
    } else if (t >= 32 && t < 42) {
        int o = t - 32, ch = g * 10 + o;
        float inv = g2[ch] * rsqrtf(v2[ch] + 1e-5f);
        s_a2[o] = inv;
        s_c2[o] = b2[ch] * inv + be2[ch] - m2[ch] * inv;
    }

    // ---- coalesced x staging: fp32 swizzled rows + fp16 channel-major copy ----
    {
        const float* xg = x + ((size_t)img * 256 + g * 32) * 16384 + px0;
        #pragma unroll
        for (int it = 0; it < 4; ++it) {
            int c = wq * 4 + it;
            int q = c >> 2, wrd = c & 3;
            const float* src = xg + (size_t)c * 16384;
            #pragma unroll
            for (int seg = 0; seg < 4; ++seg) {
                int p = (lane + seg * 32) * 2;           // even pixel
                float2 v2 = *(const float2*)(src + p);
                int qs = ((q ^ ((p >> 3) & 7)) << 2) + wrd;
                s_px[p * 36 + qs]       = v2.x;
                s_px[(p + 1) * 36 + qs] = v2.y;
                __half2 hx = __floats2half2_rn(v2.x, v2.y);
                *(uint*)(x_h + c * 264 + p) = *(uint*)&hx;
            }
        }
    }
    __syncthreads();

    // ---- conv1 -> bn -> tanh -> conv2 -> bn -> g_mn (fp16), scalar fp32 ----
    {
        const int sw = (t >> 3) & 7;
        float* xrow = s_px + t * 36;
        ulonglong2 xr[8];
        #pragma unroll
        for (int q = 0; q < 8; q++)
            xr[q] = *(const ulonglong2*)(xrow + ((q ^ sw) << 2));

        ull acc[8];
        #pragma unroll
        for (int o = 0; o < 8; o++) acc[o] = 0ULL;
        #pragma unroll
        for (int q = 0; q < 8; q++) {
            #pragma unroll
            for (int o = 0; o < 8; o++) {
                ulonglong2 wp = *(const ulonglong2*)(s_w1g + o * 32 + q * 4);
                acc[o] = fma2(xr[q].x, wp.x, acc[o]);
                acc[o] = fma2(xr[q].y, wp.y, acc[o]);
            }
        }
        float tv[8];
        #pragma unroll
        for (int o = 0; o < 8; o++)
            tv[o] = ftanh(hadd2(acc[o]) * s_a1[o] + s_c1[o]);

        __half* mb = g_mn + ((size_t)img * 80 + g * 10) * 16384 + px0 + t;
        #pragma unroll
        for (int o2 = 0; o2 < 10; o2++) {
            float a = 0.f;
            #pragma unroll
            for (int o = 0; o < 8; o++) a += tv[o] * s_w2g[o2 * 8 + o];
            mb[(size_t)o2 * 16384] = __float2half_rn(a * s_a2[o2] + s_c2[o2]);
        }
    }

    // ---- v = wv @ x via HMMA m16n8k16 (fp16 in, fp32 acc) ----
    // warp w: px tile [w*32, w*32+32), all 32 co. 2 mt x 4 nt x 2 kt mma.
    {
        const int r    = lane & 7;
        const int sub2 = (lane >> 3) & 1;
        const int px_base = wq * 32;
        const uint wh_base = (uint)__cvta_generic_to_shared(w_h);
        const uint xh_base = (uint)__cvta_generic_to_shared(x_h);

        #pragma unroll
        for (int mt = 0; mt < 2; mt++) {
            uint a[2][4];
            #pragma unroll
            for (int kt = 0; kt < 2; kt++) {
                int row = mt * 16 + r + ((lane >> 3) & 1) * 8;
                int col = kt * 16 + ((lane >> 4) & 1) * 8;
                uint addr = wh_base + (uint)(row * 40 + col) * 2u;
                asm volatile(
                    "ldmatrix.sync.aligned.m8n8.x4.shared.b16 {%0,%1,%2,%3}, [%4];"
                    : "=r"(a[kt][0]), "=r"(a[kt][1]), "=r"(a[kt][2]), "=r"(a[kt][3])
                    : "r"(addr));
            }
            #pragma unroll
            for (int nt = 0; nt < 4; nt++) {
                float c0 = 0.f, c1 = 0.f, c2 = 0.f, c3 = 0.f;
                #pragma unroll
                for (int kt = 0; kt < 2; kt++) {
                    int krow = kt * 16 + r + sub2 * 8;
                    uint baddr = xh_base + (uint)(krow * 264 + px_base + nt * 8) * 2u;
                    uint b0, b1;
                    asm volatile(
                        "ldmatrix.sync.aligned.m8n8.x2.trans.shared.b16 {%0,%1}, [%2];"
                        : "=r"(b0), "=r"(b1) : "r"(baddr));
                    asm volatile(
                        "mma.sync.aligned.m16n8k16.row.col.f32.f16.f16.f32 "
                        "{%0,%1,%2,%3}, {%4,%5,%6,%7}, {%8,%9}, {%0,%1,%2,%3};"
                        : "+f"(c0), "+f"(c1), "+f"(c2), "+f"(c3)
                        : "r"(a[kt][0]), "r"(a[kt][1]), "r"(a[kt][2]), "r"(a[kt][3]),
                          "r"(b0), "r"(b1));
                }
                // C frag -> s_vh [px][co] pitch 40
                int pxl  = px_base + nt * 8 + (lane & 3) * 2;
                int col0 = mt * 16 + (lane >> 2);
                s_vh[pxl * 40 + col0]           = __float2half_rn(c0);
                s_vh[(pxl + 1) * 40 + col0]     = __float2half_rn(c1);
                s_vh[pxl * 40 + col0 + 8]       = __float2half_rn(c2);
                s_vh[(pxl + 1) * 40 + col0 + 8] = __float2half_rn(c3);
            }
        }
    }
    __syncthreads();

    // ---- coalesced fp16 store of v: warp writes 512B contiguous ----
    __half* vplane = g_v + ((size_t)(img * 8 + g) * 16384 + px0) * 32;
    #pragma unroll
    for (int i = 0; i < 4; i++) {
        int idx = t + i * 256;          // 1024 items: 256 px x 4 chunks of 8 co
        int p = idx >> 2, q = idx & 3;
        uint4 v4 = *(const uint4*)(s_vh + p * 40 + q * 8);
        *(uint4*)(vplane + p * 32 + q * 8) = v4;
    }
}

// ============================ Kernel M ============================
// grid (8, 8, 16): z = img*8 + g. block 256 (one thread per center pixel).
__global__ __launch_bounds__(256, 4)
void combine_kernel(float* __restrict__ out)
{
    __shared__ __align__(16) float s_v[324 * 36];   // [hp][co] pitch 36 (fp32)

    const int t   = threadIdx.x;
    const int ty  = t >> 4, tx = t & 15;
    const int w0  = blockIdx.x * 16;
    const int h0  = blockIdx.y * 16;
    const int img = blockIdx.z >> 3;
    const int g   = blockIdx.z & 7;
    const int h   = h0 + ty, w = w0 + tx;
    const int px  = h * 128 + w;

    // ---- v halo gather: 16B loads (8 fp16 channels per item) ----
    const __half* vt = g_v + (size_t)(img * 8 + g) * (16384u * 32u);
    #pragma unroll
    for (int i = 0; i < 6; i++) {
        int idx = t + i * 256;          // 1296 items = 324 px * 4 chunks of 8ch
        if (idx < 1296) {
            int hp = idx >> 2, q = idx & 3;
            int hy = hp / 18, hx = hp - hy * 18;
            int hh = h0 + hy - 1, ww = w0 + hx - 1;
            uint4 raw = make_uint4(0u, 0u, 0u, 0u);
            if (((unsigned)hh < 128u) & ((unsigned)ww < 128u))
                raw = *(const uint4*)(vt + (size_t)(hh * 128 + ww) * 32 + q * 8);
            float2 f0 = __half22float2(*(__half2*)&raw.x);
            float2 f1 = __half22float2(*(__half2*)&raw.y);
            float2 f2 = __half22float2(*(__half2*)&raw.z);
            float2 f3 = __half22float2(*(__half2*)&raw.w);
            float* dst = s_v + hp * 36 + q * 8;
            *(float4*)(dst)     = make_float4(f0.x, f0.y, f1.x, f1.y);
            *(float4*)(dst + 4) = make_float4(f2.x, f2.y, f3.x, f3.y);
        }
    }

    // ---- logits: mask (9 strided coalesced) + neighbor (9 predicated), fp16 ----
    float a[9];
    {
        const __half* nbg   = g_mn + ((size_t)img * 80 + g) * 16384;
        const __half* mbase = g_mn + ((size_t)img * 80 + 8 + g * 9) * 16384 + px;
        #pragma unroll
        for (int k = 0; k < 9; k++) {
            int i = k / 3, j = k - i * 3;
            int hh = h + i - 1, ww = w + j - 1;
            float nb = 0.f;
            if (((unsigned)hh < 128u) & ((unsigned)ww < 128u))
                nb = __half2float(nbg[hh * 128 + ww]);
            a[k] = __half2float(mbase[(size_t)k * 16384]) + nb;
        }
        float mx = a[0];
        #pragma unroll
        for (int k = 1; k < 9; k++) mx = fmaxf(mx, a[k]);
        float s = 0.f;
        #pragma unroll
        for (int k = 0; k < 9; k++) { a[k] = __expf(a[k] - mx); s += a[k]; }
        float inv = 1.f / s;
        #pragma unroll
        for (int k = 0; k < 9; k++) a[k] *= inv;
    }
    __syncthreads();

    // ---- combine: out[c] = sum_k a[k] * v[c] at neighbor k ----
    {
        int hpk[9];
        #pragma unroll
        for (int k = 0; k < 9; k++) {
            int i = k / 3, j = k - i * 3;
            hpk[k] = ((ty + i) * 18 + (tx + j)) * 36;
        }
        float* ob = out + ((size_t)img * 256 + g * 32) * 16384 + px;
        #pragma unroll
        for (int c4 = 0; c4 < 8; c4++) {
            float ax = 0.f, ay = 0.f, az = 0.f, aw = 0.f;
            #pragma unroll
            for (int k = 0; k < 9; k++) {
                float4 vv = *(const float4*)(s_v + hpk[k] + c4 * 4);
                ax += a[k] * vv.x; ay += a[k] * vv.y;
                az += a[k] * vv.z; aw += a[k] * vv.w;
            }
            ob[(size_t)(c4 * 4 + 0) * 16384] = ax;
            ob[(size_t)(c4 * 4 + 1) * 16384] = ay;
            ob[(size_t)(c4 * 4 + 2) * 16384] = az;
            ob[(size_t)(c4 * 4 + 3) * 16384] = aw;
        }
    }
}

extern "C" void kernel_launch(void* const* d_in, const int* in_sizes, int n_in,
                              void* d_out, int out_size) {
    const float* x   = (const float*)d_in[0];
    const float* w1  = (const float*)d_in[1];
    const float* b1  = (const float*)d_in[2];
    const float* g1  = (const float*)d_in[3];
    const float* be1 = (const float*)d_in[4];
    const float* m1  = (const float*)d_in[5];
    const float* v1  = (const float*)d_in[6];
    const float* w2  = (const float*)d_in[7];
    const float* b2  = (const float*)d_in[8];
    const float* g2  = (const float*)d_in[9];
    const float* be2 = (const float*)d_in[10];
    const float* m2  = (const float*)d_in[11];
    const float* v2  = (const float*)d_in[12];
    const float* wv  = (const float*)d_in[13];
    float* out = (float*)d_out;

    static int inited = 0;
    if (!inited) {
        cudaFuncSetAttribute(stage1_kernel,
                             cudaFuncAttributeMaxDynamicSharedMemorySize, S_SMEM);
        inited = 1;
    }

    stage1_kernel<<<dim3(64, 8, 2), 256, S_SMEM>>>(x, w1, b1, g1, be1, m1, v1,
                                                   w2, b2, g2, be2, m2, v2, wv);
    combine_kernel<<<dim3(8, 8, 16), 256>>>(out);
}

// round 17
// speedup vs baseline: 1.4408x; 1.1527x over previous
#include <cuda_runtime.h>
#include <cuda_fp16.h>

// LocalAttn, 2-kernel pipeline for GB300 (sm_103a), round 17.
// = round-16 (best, 43.0us) + two crossbar fixes:
//   stage1: register-transposed staging (8 LDG.128 + conflict-free STS.128
//           quad stores; the old STS.32 path was inherently 4-way conflicted).
//   combine: v halo kept fp16 in smem (raw uint4 gather copy; 36 LDS.128
//           instead of 72 in the attention loop; cvt at consume on ALU pipe).

typedef unsigned long long ull;
typedef unsigned int uint;

__device__ __half g_v [2u * 8u * 16384u * 32u]; // [img][g][px][32]  16.8 MB
__device__ __half g_mn[2u * 80u * 16384u];      // [img][ch][px]      5.2 MB

__device__ __forceinline__ ull fma2(ull a, ull b, ull c) {
    ull d;
    asm("fma.rn.f32x2 %0, %1, %2, %3;" : "=l"(d) : "l"(a), "l"(b), "l"(c));
    return d;
}
__device__ __forceinline__ float hadd2(ull a) {
    float x, y;
    asm("mov.b64 {%0,%1}, %2;" : "=f"(x), "=f"(y) : "l"(a));
    return x + y;
}
__device__ __forceinline__ float ftanh(float x) {
    float e = __expf(-2.f * fabsf(x));
    float r = __fdividef(1.f - e, 1.f + e);
    return copysignf(r, x);
}

// ---- stage1 dynamic smem layout (bytes) ----
// s_px  fp32 [256*36]  @0      (36864)  swizzled x rows, conv1 input
// s_w1g fp32 [256]     @36864  (1024)
// s_w2g fp32 [80]      @37888  (320)
// s_a1/c1/a2/c2        @38208  (144) -> pad 38400
// x_h  half [32][264]  @38400  (16896)  channel-major fp16 x for HMMA B
// w_h  half [32][40]   @55296  (2560)   wv fp16 for HMMA A
// s_vh half [256][40]  @57856  (20480)  v writeout tile [px][co], pitch 40
static const int S_SMEM = 78336;

// ============================ Kernel A ============================
// grid (64, 8, 2) = (px chunk, group, img), block 256, one thread per pixel.
__global__ __launch_bounds__(256, 2)
void stage1_kernel(
    const float* __restrict__ x,
    const float* __restrict__ w1, const float* __restrict__ b1,
    const float* __restrict__ g1, const float* __restrict__ be1,
    const float* __restrict__ m1, const float* __restrict__ v1,
    const float* __restrict__ w2, const float* __restrict__ b2,
    const float* __restrict__ g2, const float* __restrict__ be2,
    const float* __restrict__ m2, const float* __restrict__ v2,
    const float* __restrict__ wv)
{
    extern __shared__ __align__(16) char smraw[];
    float*  s_px  = (float*)(smraw);
    float*  s_w1g = (float*)(smraw + 36864);
    float*  s_w2g = (float*)(smraw + 37888);
    float*  s_a1  = (float*)(smraw + 38208);
    float*  s_c1  = (float*)(smraw + 38240);
    float*  s_a2  = (float*)(smraw + 38272);
    float*  s_c2  = (float*)(smraw + 38312);
    __half* x_h   = (__half*)(smraw + 38400);
    __half* w_h   = (__half*)(smraw + 55296);
    __half* s_vh  = (__half*)(smraw + 57856);

    const int t    = threadIdx.x;
    const int lane = t & 31;
    const int wq   = t >> 5;
    const int px0  = blockIdx.x * 256;
    const int g    = blockIdx.y;
    const int img  = blockIdx.z;

    // weights + folded BN params
    s_w1g[t] = w1[g * 256 + t];
    for (int i = t; i < 1024; i += 256) {
        int co = i >> 5, ci = i & 31;
        w_h[co * 40 + ci] = __float2half_rn(wv[g * 1024 + i]);
    }
    if (t < 80) s_w2g[t] = w2[g * 80 + t];
    if (t < 8) {
        int ch = g * 8 + t;
        float inv = g1[ch] * rsqrtf(v1[ch] + 1e-5f);
        s_a1[t] = inv;
        s_c1[t] = b1[ch] * inv + be1[ch] - m1[ch] * inv;
    } else if (t >= 32 && t < 42) {
        int o = t - 32, ch = g * 10 + o;
        float inv = g2[ch] * rsqrtf(v2[ch] + 1e-5f);
        s_a2[o] = inv;
        s_c2[o] = b2[ch] * inv + be2[ch] - m2[ch] * inv;
    }

    // ---- staging: warp wq loads its quad (channels 4wq..4wq+3), 4 px/lane,
    //      register-transpose -> conflict-free STS.128 + fp16 channel copy ----
    {
        const float* xg = x + ((size_t)img * 256 + g * 32) * 16384 + px0;
        #pragma unroll
        for (int seg = 0; seg < 2; ++seg) {
            int p = (lane + seg * 32) * 4;
            int s = (p >> 3) & 7;
            float4 vc[4];
            #pragma unroll
            for (int it = 0; it < 4; ++it)
                vc[it] = *(const float4*)(xg + (size_t)(wq * 4 + it) * 16384 + p);

            int qs = (wq ^ s) << 2;
            *(float4*)(s_px + (p + 0) * 36 + qs) =
                make_float4(vc[0].x, vc[1].x, vc[2].x, vc[3].x);
            *(float4*)(s_px + (p + 1) * 36 + qs) =
                make_float4(vc[0].y, vc[1].y, vc[2].y, vc[3].y);
            *(float4*)(s_px + (p + 2) * 36 + qs) =
                make_float4(vc[0].z, vc[1].z, vc[2].z, vc[3].z);
            *(float4*)(s_px + (p + 3) * 36 + qs) =
                make_float4(vc[0].w, vc[1].w, vc[2].w, vc[3].w);

            #pragma unroll
            for (int it = 0; it < 4; ++it) {
                int c = wq * 4 + it;
                __half2 h0 = __floats2half2_rn(vc[it].x, vc[it].y);
                __half2 h1 = __floats2half2_rn(vc[it].z, vc[it].w);
                uint2 st;
                st.x = *(uint*)&h0;
                st.y = *(uint*)&h1;
                *(uint2*)(x_h + c * 264 + p) = st;
            }
        }
    }
    __syncthreads();

    // ---- conv1 -> bn -> tanh -> conv2 -> bn -> g_mn (fp16), scalar fp32 ----
    {
        const int sw = (t >> 3) & 7;
        float* xrow = s_px + t * 36;
        ulonglong2 xr[8];
        #pragma unroll
        for (int q = 0; q < 8; q++)
            xr[q] = *(const ulonglong2*)(xrow + ((q ^ sw) << 2));

        ull acc[8];
        #pragma unroll
        for (int o = 0; o < 8; o++) acc[o] = 0ULL;
        #pragma unroll
        for (int q = 0; q < 8; q++) {
            #pragma unroll
            for (int o = 0; o < 8; o++) {
                ulonglong2 wp = *(const ulonglong2*)(s_w1g + o * 32 + q * 4);
                acc[o] = fma2(xr[q].x, wp.x, acc[o]);
                acc[o] = fma2(xr[q].y, wp.y, acc[o]);
            }
        }
        float tv[8];
        #pragma unroll
        for (int o = 0; o < 8; o++)
            tv[o] = ftanh(hadd2(acc[o]) * s_a1[o] + s_c1[o]);

        __half* mb = g_mn + ((size_t)img * 80 + g * 10) * 16384 + px0 + t;
        #pragma unroll
        for (int o2 = 0; o2 < 10; o2++) {
            float a = 0.f;
            #pragma unroll
            for (int o = 0; o < 8; o++) a += tv[o] * s_w2g[o2 * 8 + o];
            mb[(size_t)o2 * 16384] = __float2half_rn(a * s_a2[o2] + s_c2[o2]);
        }
    }

    // ---- v = wv @ x via HMMA m16n8k16 (fp16 in, fp32 acc) ----
    {
        const int r    = lane & 7;
        const int sub2 = (lane >> 3) & 1;
        const int px_base = wq * 32;
        const uint wh_base = (uint)__cvta_generic_to_shared(w_h);
        const uint xh_base = (uint)__cvta_generic_to_shared(x_h);

        #pragma unroll
        for (int mt = 0; mt < 2; mt++) {
            uint a[2][4];
            #pragma unroll
            for (int kt = 0; kt < 2; kt++) {
                int row = mt * 16 + r + ((lane >> 3) & 1) * 8;
                int col = kt * 16 + ((lane >> 4) & 1) * 8;
                uint addr = wh_base + (uint)(row * 40 + col) * 2u;
                asm volatile(
                    "ldmatrix.sync.aligned.m8n8.x4.shared.b16 {%0,%1,%2,%3}, [%4];"
                    : "=r"(a[kt][0]), "=r"(a[kt][1]), "=r"(a[kt][2]), "=r"(a[kt][3])
                    : "r"(addr));
            }
            #pragma unroll
            for (int nt = 0; nt < 4; nt++) {
                float c0 = 0.f, c1 = 0.f, c2 = 0.f, c3 = 0.f;
                #pragma unroll
                for (int kt = 0; kt < 2; kt++) {
                    int krow = kt * 16 + r + sub2 * 8;
                    uint baddr = xh_base + (uint)(krow * 264 + px_base + nt * 8) * 2u;
                    uint b0, b1;
                    asm volatile(
                        "ldmatrix.sync.aligned.m8n8.x2.trans.shared.b16 {%0,%1}, [%2];"
                        : "=r"(b0), "=r"(b1) : "r"(baddr));
                    asm volatile(
                        "mma.sync.aligned.m16n8k16.row.col.f32.f16.f16.f32 "
                        "{%0,%1,%2,%3}, {%4,%5,%6,%7}, {%8,%9}, {%0,%1,%2,%3};"
                        : "+f"(c0), "+f"(c1), "+f"(c2), "+f"(c3)
                        : "r"(a[kt][0]), "r"(a[kt][1]), "r"(a[kt][2]), "r"(a[kt][3]),
                          "r"(b0), "r"(b1));
                }
                int pxl  = px_base + nt * 8 + (lane & 3) * 2;
                int col0 = mt * 16 + (lane >> 2);
                s_vh[pxl * 40 + col0]           = __float2half_rn(c0);
                s_vh[(pxl + 1) * 40 + col0]     = __float2half_rn(c1);
                s_vh[pxl * 40 + col0 + 8]       = __float2half_rn(c2);
                s_vh[(pxl + 1) * 40 + col0 + 8] = __float2half_rn(c3);
            }
        }
    }
    __syncthreads();

    // ---- coalesced fp16 store of v ----
    __half* vplane = g_v + ((size_t)(img * 8 + g) * 16384 + px0) * 32;
    #pragma unroll
    for (int i = 0; i < 4; i++) {
        int idx = t + i * 256;          // 1024 items: 256 px x 4 chunks of 8 co
        int p = idx >> 2, q = idx & 3;
        uint4 v4 = *(const uint4*)(s_vh + p * 40 + q * 8);
        *(uint4*)(vplane + p * 32 + q * 8) = v4;
    }
}

// ============================ Kernel M ============================
// grid (8, 8, 16): z = img*8 + g. block 256 (one thread per center pixel).
__global__ __launch_bounds__(256, 4)
void combine_kernel(float* __restrict__ out)
{
    __shared__ __align__(16) __half s_vh[324 * 40];   // [hp][co] pitch 40, fp16

    const int t   = threadIdx.x;
    const int ty  = t >> 4, tx = t & 15;
    const int w0  = blockIdx.x * 16;
    const int h0  = blockIdx.y * 16;
    const int img = blockIdx.z >> 3;
    const int g   = blockIdx.z & 7;
    const int h   = h0 + ty, w = w0 + tx;
    const int px  = h * 128 + w;

    // ---- v halo gather: raw fp16 uint4 copy (no conversion) ----
    const __half* vt = g_v + (size_t)(img * 8 + g) * (16384u * 32u);
    #pragma unroll
    for (int i = 0; i < 6; i++) {
        int idx = t + i * 256;          // 1296 items = 324 px * 4 chunks of 8ch
        if (idx < 1296) {
            int hp = idx >> 2, q = idx & 3;
            int hy = hp / 18, hx = hp - hy * 18;
            int hh = h0 + hy - 1, ww = w0 + hx - 1;
            uint4 raw = make_uint4(0u, 0u, 0u, 0u);
            if (((unsigned)hh < 128u) & ((unsigned)ww < 128u))
                raw = *(const uint4*)(vt + (size_t)(hh * 128 + ww) * 32 + q * 8);
            *(uint4*)(s_vh + hp * 40 + q * 8) = raw;
        }
    }

    // ---- logits: mask (9 strided coalesced) + neighbor (9 predicated), fp16 ----
    float a[9];
    {
        const __half* nbg   = g_mn + ((size_t)img * 80 + g) * 16384;
        const __half* mbase = g_mn + ((size_t)img * 80 + 8 + g * 9) * 16384 + px;
        #pragma unroll
        for (int k = 0; k < 9; k++) {
            int i = k / 3, j = k - i * 3;
            int hh = h + i - 1, ww = w + j - 1;
            float nb = 0.f;
            if (((unsigned)hh < 128u) & ((unsigned)ww < 128u))
                nb = __half2float(nbg[hh * 128 + ww]);
            a[k] = __half2float(mbase[(size_t)k * 16384]) + nb;
        }
        float mx = a[0];
        #pragma unroll
        for (int k = 1; k < 9; k++) mx = fmaxf(mx, a[k]);
        float s = 0.f;
        #pragma unroll
        for (int k = 0; k < 9; k++) { a[k] = __expf(a[k] - mx); s += a[k]; }
        float inv = 1.f / s;
        #pragma unroll
        for (int k = 0; k < 9; k++) a[k] *= inv;
    }
    __syncthreads();

    // ---- combine: out[c] = sum_k a[k] * v[c] at neighbor k (fp16 LDS) ----
    {
        int hpk[9];
        #pragma unroll
        for (int k = 0; k < 9; k++) {
            int i = k / 3, j = k - i * 3;
            hpk[k] = ((ty + i) * 18 + (tx + j)) * 40;
        }
        float* ob = out + ((size_t)img * 256 + g * 32) * 16384 + px;
        #pragma unroll
        for (int c8 = 0; c8 < 4; c8++) {
            float acc[8];
            #pragma unroll
            for (int m = 0; m < 8; m++) acc[m] = 0.f;
            #pragma unroll
            for (int k = 0; k < 9; k++) {
                uint4 raw = *(const uint4*)(s_vh + hpk[k] + c8 * 8);
                float2 f0 = __half22float2(*(__half2*)&raw.x);
                float2 f1 = __half22float2(*(__half2*)&raw.y);
                float2 f2 = __half22float2(*(__half2*)&raw.z);
                float2 f3 = __half22float2(*(__half2*)&raw.w);
                acc[0] += a[k] * f0.x; acc[1] += a[k] * f0.y;
                acc[2] += a[k] * f1.x; acc[3] += a[k] * f1.y;
                acc[4] += a[k] * f2.x; acc[5] += a[k] * f2.y;
                acc[6] += a[k] * f3.x; acc[7] += a[k] * f3.y;
            }
            #pragma unroll
            for (int m = 0; m < 8; m++)
                ob[(size_t)(c8 * 8 + m) * 16384] = acc[m];
        }
    }
}

extern "C" void kernel_launch(void* const* d_in, const int* in_sizes, int n_in,
                              void* d_out, int out_size) {
    const float* x   = (const float*)d_in[0];
    const float* w1  = (const float*)d_in[1];
    const float* b1  = (const float*)d_in[2];
    const float* g1  = (const float*)d_in[3];
    const float* be1 = (const float*)d_in[4];
    const float* m1  = (const float*)d_in[5];
    const float* v1  = (const float*)d_in[6];
    const float* w2  = (const float*)d_in[7];
    const float* b2  = (const float*)d_in[8];
    const float* g2  = (const float*)d_in[9];
    const float* be2 = (const float*)d_in[10];
    const float* m2  = (const float*)d_in[11];
    const float* v2  = (const float*)d_in[12];
    const float* wv  = (const float*)d_in[13];
    float* out = (float*)d_out;

    static int inited = 0;
    if (!inited) {
        cudaFuncSetAttribute(stage1_kernel,
                             cudaFuncAttributeMaxDynamicSharedMemorySize, S_SMEM);
        inited = 1;
    }

    stage1_kernel<<<dim3(64, 8, 2), 256, S_SMEM>>>(x, w1, b1, g1, be1, m1, v1,
                                                   w2, b2, g2, be2, m2, v2, wv);
    combine_kernel<<<dim3(8, 8, 16), 256>>>(out);
}